// round 1
// baseline (speedup 1.0000x reference)
#include <cuda_runtime.h>
#include <math.h>

#define B_   2
#define S_   2048
#define HID_ 4096
#define H_   32
#define KH_  8
#define D_   128
#define WIN_ 1024
#define M_TOK (B_*S_)   // 4096 tokens

// Scratch (allocation-free rule: __device__ globals)
__device__ float g_q [M_TOK * H_  * D_];   // [tok][h*128+d]
__device__ float g_k [M_TOK * KH_ * D_];
__device__ float g_v [M_TOK * KH_ * D_];
__device__ float g_ao[M_TOK * H_  * D_];

// ---------------------------------------------------------------------------
// SGEMM: C[M,N] = A[M,K] @ B[K,N], fp32. Requires M%128==0, N%128==0, K%16==0.
// 128x128 block tile, BK=16, 256 threads, 8x8 microtile per thread.
// ---------------------------------------------------------------------------
__global__ __launch_bounds__(256, 2)
void sgemm_kernel(const float* __restrict__ A, const float* __restrict__ Bm,
                  float* __restrict__ C, int M, int N, int K)
{
    __shared__ float As[16 * 132];   // As[k][m], padded row 132
    __shared__ float Bs[16 * 132];   // Bs[k][n], padded row 132

    const int tid = threadIdx.x;
    const int tx  = tid & 15;
    const int ty  = tid >> 4;
    const int m0  = blockIdx.y * 128;
    const int n0  = blockIdx.x * 128;

    float acc[8][8];
    #pragma unroll
    for (int i = 0; i < 8; i++)
        #pragma unroll
        for (int j = 0; j < 8; j++) acc[i][j] = 0.0f;

    const int nk = K >> 4;
    for (int kt = 0; kt < nk; kt++) {
        // Load A tile (128 x 16), store transposed As[k][m]
        #pragma unroll
        for (int l = 0; l < 2; l++) {
            int idx = tid + l * 256;          // 0..511
            int row = idx >> 2;               // 0..127
            int c4  = (idx & 3) << 2;         // 0,4,8,12
            float4 av = *reinterpret_cast<const float4*>(
                &A[(size_t)(m0 + row) * K + kt * 16 + c4]);
            As[(c4 + 0) * 132 + row] = av.x;
            As[(c4 + 1) * 132 + row] = av.y;
            As[(c4 + 2) * 132 + row] = av.z;
            As[(c4 + 3) * 132 + row] = av.w;
        }
        // Load B tile (16 x 128), direct
        #pragma unroll
        for (int l = 0; l < 2; l++) {
            int idx = tid + l * 256;          // 0..511
            int row = idx >> 5;               // 0..15
            int c   = (idx & 31) << 2;        // 0..124
            *reinterpret_cast<float4*>(&Bs[row * 132 + c]) =
                *reinterpret_cast<const float4*>(
                    &Bm[(size_t)(kt * 16 + row) * N + n0 + c]);
        }
        __syncthreads();

        #pragma unroll
        for (int kk = 0; kk < 16; kk++) {
            float4 a0 = *reinterpret_cast<const float4*>(&As[kk * 132 + ty * 8]);
            float4 a1 = *reinterpret_cast<const float4*>(&As[kk * 132 + ty * 8 + 4]);
            float4 b0 = *reinterpret_cast<const float4*>(&Bs[kk * 132 + tx * 8]);
            float4 b1 = *reinterpret_cast<const float4*>(&Bs[kk * 132 + tx * 8 + 4]);
            float a[8] = {a0.x, a0.y, a0.z, a0.w, a1.x, a1.y, a1.z, a1.w};
            float b[8] = {b0.x, b0.y, b0.z, b0.w, b1.x, b1.y, b1.z, b1.w};
            #pragma unroll
            for (int i = 0; i < 8; i++)
                #pragma unroll
                for (int j = 0; j < 8; j++)
                    acc[i][j] = fmaf(a[i], b[j], acc[i][j]);
        }
        __syncthreads();
    }

    #pragma unroll
    for (int i = 0; i < 8; i++) {
        int row = m0 + ty * 8 + i;
        float4 o0 = make_float4(acc[i][0], acc[i][1], acc[i][2], acc[i][3]);
        float4 o1 = make_float4(acc[i][4], acc[i][5], acc[i][6], acc[i][7]);
        *reinterpret_cast<float4*>(&C[(size_t)row * N + n0 + tx * 8])     = o0;
        *reinterpret_cast<float4*>(&C[(size_t)row * N + n0 + tx * 8 + 4]) = o1;
    }
}

// ---------------------------------------------------------------------------
// RoPE (in-place on g_q, g_k). One thread per (token, head, pair d<64).
// out[d]    = x[d]*cos - x[d+64]*sin
// out[d+64] = x[d+64]*cos + x[d]*sin,  angle = pos * theta^(-2d/128)
// ---------------------------------------------------------------------------
__global__ void rope_kernel(const int* __restrict__ pos)
{
    int idx = blockIdx.x * blockDim.x + threadIdx.x;
    const int nq = M_TOK * H_  * 64;
    const int nk = M_TOK * KH_ * 64;
    float* base;
    int t, dp;
    if (idx < nq) {
        dp = idx & 63; int r = idx >> 6;
        int h = r & 31; t = r >> 5;
        base = &g_q[((size_t)t * H_ + h) * D_];
    } else {
        idx -= nq;
        if (idx >= nk) return;
        dp = idx & 63; int r = idx >> 6;
        int h = r & 7;  t = r >> 3;
        base = &g_k[((size_t)t * KH_ + h) * D_];
    }
    float p   = (float)pos[t];
    // inv_freq = exp2(-(2*dp/128) * log2(1e6)),  log2(1e6)=19.9315685693...
    float ang = p * exp2f((float)dp * (-19.931568569324174f / 64.0f));
    float sn, cs;
    sincosf(ang, &sn, &cs);
    float x1 = base[dp], x2 = base[dp + 64];
    base[dp]      = x1 * cs - x2 * sn;
    base[dp + 64] = x2 * cs + x1 * sn;
}

// ---------------------------------------------------------------------------
// Flash attention, sliding window causal (j <= i, i-j < 1024), GQA (kh=h/4).
// Block: 256 threads, Q tile 64 rows, K tile 64 cols, online softmax.
// Thread (tx,ty): score microtile rows ty*4..+4 x cols tx*4..+4;
//                 O microtile rows ty*4..+4 x dims tx*8..+8.
// Row stats reduced over the 16 tx-lanes via shfl_xor (lanes form half-warps).
// ---------------------------------------------------------------------------
#define ATT_SMEM_FLOATS (64*129 + 64*129 + 64*132 + 64*68)
#define ATT_SMEM_BYTES  (ATT_SMEM_FLOATS * 4)

__global__ __launch_bounds__(256, 1)
void attn_kernel()
{
    extern __shared__ float sm[];
    float* Qs = sm;                       // [64][129]
    float* Ks = Qs + 64 * 129;            // [64][129]
    float* Vs = Ks + 64 * 129;            // [64][132]
    float* Ps = Vs + 64 * 132;            // [64][68]

    const int tid = threadIdx.x;
    const int tx  = tid & 15;
    const int ty  = tid >> 4;
    const int tm0 = ty * 4;
    const int tn0 = tx * 4;
    const int i0  = blockIdx.x * 64;
    const int h   = blockIdx.y;
    const int b   = blockIdx.z;
    const int kh  = h >> 2;

    const float qscale = 0.08838834764831845f;   // 1/sqrt(128)
    for (int i = tid; i < 64 * 128; i += 256) {
        int r = i >> 7, d = i & 127;
        Qs[r * 129 + d] =
            g_q[(((size_t)(b * S_ + i0 + r)) * H_ + h) * D_ + d] * qscale;
    }

    float acc[4][8];
    #pragma unroll
    for (int i = 0; i < 4; i++)
        #pragma unroll
        for (int j = 0; j < 8; j++) acc[i][j] = 0.0f;
    float rm[4] = {-1e30f, -1e30f, -1e30f, -1e30f};
    float rl[4] = {0.f, 0.f, 0.f, 0.f};

    int lo  = i0 - WIN_ + 1; if (lo < 0) lo = 0;
    int jt0 = lo >> 6;
    int jt1 = i0 >> 6;

    for (int jt = jt0; jt <= jt1; jt++) {
        int j0 = jt << 6;
        __syncthreads();   // previous iteration done with Ks/Vs/Ps
        for (int i = tid; i < 64 * 128; i += 256) {
            int r = i >> 7, d = i & 127;
            size_t tok = (size_t)(b * S_ + j0 + r);
            Ks[r * 129 + d] = g_k[(tok * KH_ + kh) * D_ + d];
            Vs[r * 132 + d] = g_v[(tok * KH_ + kh) * D_ + d];
        }
        __syncthreads();

        // ---- scores S = Q K^T (64x64), microtile 4x4 ----
        float s[4][4];
        #pragma unroll
        for (int i = 0; i < 4; i++)
            #pragma unroll
            for (int j = 0; j < 4; j++) s[i][j] = 0.0f;

        #pragma unroll 4
        for (int d = 0; d < 128; d++) {
            float a0 = Qs[(tm0 + 0) * 129 + d];
            float a1 = Qs[(tm0 + 1) * 129 + d];
            float a2 = Qs[(tm0 + 2) * 129 + d];
            float a3 = Qs[(tm0 + 3) * 129 + d];
            float b0 = Ks[(tn0 + 0) * 129 + d];
            float b1 = Ks[(tn0 + 1) * 129 + d];
            float b2 = Ks[(tn0 + 2) * 129 + d];
            float b3 = Ks[(tn0 + 3) * 129 + d];
            s[0][0] = fmaf(a0, b0, s[0][0]); s[0][1] = fmaf(a0, b1, s[0][1]);
            s[0][2] = fmaf(a0, b2, s[0][2]); s[0][3] = fmaf(a0, b3, s[0][3]);
            s[1][0] = fmaf(a1, b0, s[1][0]); s[1][1] = fmaf(a1, b1, s[1][1]);
            s[1][2] = fmaf(a1, b2, s[1][2]); s[1][3] = fmaf(a1, b3, s[1][3]);
            s[2][0] = fmaf(a2, b0, s[2][0]); s[2][1] = fmaf(a2, b1, s[2][1]);
            s[2][2] = fmaf(a2, b2, s[2][2]); s[2][3] = fmaf(a2, b3, s[2][3]);
            s[3][0] = fmaf(a3, b0, s[3][0]); s[3][1] = fmaf(a3, b1, s[3][1]);
            s[3][2] = fmaf(a3, b2, s[3][2]); s[3][3] = fmaf(a3, b3, s[3][3]);
        }

        // ---- mask + online softmax ----
        #pragma unroll
        for (int i = 0; i < 4; i++) {
            int qq = i0 + tm0 + i;
            float tmax = -1e30f;
            #pragma unroll
            for (int j = 0; j < 4; j++) {
                int kj = j0 + tn0 + j;
                if (kj > qq || (qq - kj) >= WIN_) s[i][j] = -1e30f;
                tmax = fmaxf(tmax, s[i][j]);
            }
            tmax = fmaxf(tmax, __shfl_xor_sync(0xffffffffu, tmax, 8));
            tmax = fmaxf(tmax, __shfl_xor_sync(0xffffffffu, tmax, 4));
            tmax = fmaxf(tmax, __shfl_xor_sync(0xffffffffu, tmax, 2));
            tmax = fmaxf(tmax, __shfl_xor_sync(0xffffffffu, tmax, 1));
            float mnew = fmaxf(rm[i], tmax);
            float scl  = __expf(rm[i] - mnew);
            float rs = 0.0f;
            #pragma unroll
            for (int j = 0; j < 4; j++) {
                float p = __expf(s[i][j] - mnew);
                s[i][j] = p;
                rs += p;
            }
            rs += __shfl_xor_sync(0xffffffffu, rs, 8);
            rs += __shfl_xor_sync(0xffffffffu, rs, 4);
            rs += __shfl_xor_sync(0xffffffffu, rs, 2);
            rs += __shfl_xor_sync(0xffffffffu, rs, 1);
            rl[i] = rl[i] * scl + rs;
            rm[i] = mnew;
            #pragma unroll
            for (int j = 0; j < 8; j++) acc[i][j] *= scl;
            #pragma unroll
            for (int j = 0; j < 4; j++)
                Ps[(tm0 + i) * 68 + tn0 + j] = s[i][j];
        }
        __syncthreads();   // Ps visible to all

        // ---- O += P V  (64x64 @ 64x128), microtile 4x8 ----
        #pragma unroll 2
        for (int kk = 0; kk < 64; kk++) {
            float p0 = Ps[(tm0 + 0) * 68 + kk];
            float p1 = Ps[(tm0 + 1) * 68 + kk];
            float p2 = Ps[(tm0 + 2) * 68 + kk];
            float p3 = Ps[(tm0 + 3) * 68 + kk];
            float4 v0 = *reinterpret_cast<const float4*>(&Vs[kk * 132 + tx * 8]);
            float4 v1 = *reinterpret_cast<const float4*>(&Vs[kk * 132 + tx * 8 + 4]);
            float v[8] = {v0.x, v0.y, v0.z, v0.w, v1.x, v1.y, v1.z, v1.w};
            #pragma unroll
            for (int j = 0; j < 8; j++) {
                acc[0][j] = fmaf(p0, v[j], acc[0][j]);
                acc[1][j] = fmaf(p1, v[j], acc[1][j]);
                acc[2][j] = fmaf(p2, v[j], acc[2][j]);
                acc[3][j] = fmaf(p3, v[j], acc[3][j]);
            }
        }
    }

    // ---- epilogue: O /= l, write to g_ao ----
    #pragma unroll
    for (int i = 0; i < 4; i++) {
        float inv = 1.0f / rl[i];
        size_t tok = (size_t)(b * S_ + i0 + tm0 + i);
        float* dst = &g_ao[(tok * H_ + h) * D_ + tx * 8];
        float4 o0 = make_float4(acc[i][0] * inv, acc[i][1] * inv,
                                acc[i][2] * inv, acc[i][3] * inv);
        float4 o1 = make_float4(acc[i][4] * inv, acc[i][5] * inv,
                                acc[i][6] * inv, acc[i][7] * inv);
        *reinterpret_cast<float4*>(dst)     = o0;
        *reinterpret_cast<float4*>(dst + 4) = o1;
    }
}

// ---------------------------------------------------------------------------
extern "C" void kernel_launch(void* const* d_in, const int* in_sizes, int n_in,
                              void* d_out, int out_size)
{
    const float* hidden = (const float*)d_in[0];  // [2,2048,4096]
    const int*   pos    = (const int*)  d_in[1];  // [2,2048]
    const float* wq     = (const float*)d_in[2];  // [4096,4096]
    const float* wk     = (const float*)d_in[3];  // [4096,1024]
    const float* wv     = (const float*)d_in[4];  // [4096,1024]
    const float* wo     = (const float*)d_in[5];  // [4096,4096]
    float* out = (float*)d_out;                   // [2,2048,4096]

    float *gq, *gk, *gv, *gao;
    cudaGetSymbolAddress((void**)&gq,  g_q);
    cudaGetSymbolAddress((void**)&gk,  g_k);
    cudaGetSymbolAddress((void**)&gv,  g_v);
    cudaGetSymbolAddress((void**)&gao, g_ao);

    // QKV projections
    sgemm_kernel<<<dim3(32, 32), 256>>>(hidden, wq, gq, M_TOK, H_ * D_,  HID_);
    sgemm_kernel<<<dim3( 8, 32), 256>>>(hidden, wk, gk, M_TOK, KH_ * D_, HID_);
    sgemm_kernel<<<dim3( 8, 32), 256>>>(hidden, wv, gv, M_TOK, KH_ * D_, HID_);

    // RoPE on Q and K
    {
        int total = M_TOK * H_ * 64 + M_TOK * KH_ * 64;
        rope_kernel<<<(total + 255) / 256, 256>>>(pos);
    }

    // Sliding-window attention
    cudaFuncSetAttribute(attn_kernel,
                         cudaFuncAttributeMaxDynamicSharedMemorySize,
                         ATT_SMEM_BYTES);
    attn_kernel<<<dim3(S_ / 64, H_, B_), 256, ATT_SMEM_BYTES>>>();

    // Output projection
    sgemm_kernel<<<dim3(32, 32), 256>>>(gao, wo, out, M_TOK, HID_, H_ * D_);
}

// round 3
// speedup vs baseline: 1.8756x; 1.8756x over previous
#include <cuda_runtime.h>
#include <cuda_bf16.h>
#include <math.h>
#include <stdint.h>

#define B_   2
#define S_   2048
#define HID_ 4096
#define H_   32
#define KH_  8
#define D_   128
#define WIN_ 1024
#define M_TOK (B_*S_)   // 4096 tokens

// ---------------------------------------------------------------------------
// Scratch (__device__ globals; no allocation allowed)
// ---------------------------------------------------------------------------
__device__ float g_q [M_TOK * H_  * D_];
__device__ float g_k [M_TOK * KH_ * D_];
__device__ float g_v [M_TOK * KH_ * D_];
__device__ float g_ao[M_TOK * H_  * D_];

// split-bf16 buffers
__device__ __nv_bfloat16 g_Ahi[M_TOK * HID_];
__device__ __nv_bfloat16 g_Alo[M_TOK * HID_];
__device__ __nv_bfloat16 g_Wqhi[(H_*D_)  * HID_];  // weights, [N][K]
__device__ __nv_bfloat16 g_Wqlo[(H_*D_)  * HID_];
__device__ __nv_bfloat16 g_Wkhi[(KH_*D_) * HID_];
__device__ __nv_bfloat16 g_Wklo[(KH_*D_) * HID_];
__device__ __nv_bfloat16 g_Wvhi[(KH_*D_) * HID_];
__device__ __nv_bfloat16 g_Wvlo[(KH_*D_) * HID_];
__device__ __nv_bfloat16 g_Wohi[HID_ * (H_*D_)];
__device__ __nv_bfloat16 g_Wolo[HID_ * (H_*D_)];

// ---------------------------------------------------------------------------
// PTX helpers (family-target safe: ldmatrix / mma.sync / cp.async only)
// ---------------------------------------------------------------------------
__device__ __forceinline__ uint32_t smem_u32(const void* p) {
    uint32_t a;
    asm("{ .reg .u64 t; cvta.to.shared.u64 t, %1; cvt.u32.u64 %0, t; }"
        : "=r"(a) : "l"(p));
    return a;
}
#define CP_ASYNC16(saddr, gaddr) \
    asm volatile("cp.async.cg.shared.global [%0], [%1], 16;" \
                 :: "r"(saddr), "l"(gaddr))
#define CP_COMMIT() asm volatile("cp.async.commit_group;" ::: "memory")
template <int N>
__device__ __forceinline__ void cp_wait() {
    asm volatile("cp.async.wait_group %0;" :: "n"(N) : "memory");
}
#define LDSM4(r, a) \
    asm volatile("ldmatrix.sync.aligned.m8n8.x4.shared.b16 {%0,%1,%2,%3}, [%4];" \
                 : "=r"((r)[0]), "=r"((r)[1]), "=r"((r)[2]), "=r"((r)[3]) : "r"(a))
#define MMA16816(c, a, b0v, b1v) \
    asm volatile("mma.sync.aligned.m16n8k16.row.col.f32.bf16.bf16.f32 " \
                 "{%0,%1,%2,%3}, {%4,%5,%6,%7}, {%8,%9}, {%0,%1,%2,%3};" \
                 : "+f"((c)[0]), "+f"((c)[1]), "+f"((c)[2]), "+f"((c)[3]) \
                 : "r"((a)[0]), "r"((a)[1]), "r"((a)[2]), "r"((a)[3]), \
                   "r"(b0v), "r"(b1v))

// ---------------------------------------------------------------------------
// Split fp32 -> (hi, lo) bf16, same layout. n must be /4.
// ---------------------------------------------------------------------------
__global__ void split_kernel(const float* __restrict__ in,
                             __nv_bfloat16* __restrict__ hi,
                             __nv_bfloat16* __restrict__ lo, int n4)
{
    int i = blockIdx.x * blockDim.x + threadIdx.x;
    if (i >= n4) return;
    float4 v = reinterpret_cast<const float4*>(in)[i];
    __nv_bfloat16 h0 = __float2bfloat16_rn(v.x);
    __nv_bfloat16 h1 = __float2bfloat16_rn(v.y);
    __nv_bfloat16 h2 = __float2bfloat16_rn(v.z);
    __nv_bfloat16 h3 = __float2bfloat16_rn(v.w);
    __nv_bfloat162 hp0; hp0.x = h0; hp0.y = h1;
    __nv_bfloat162 hp1; hp1.x = h2; hp1.y = h3;
    reinterpret_cast<__nv_bfloat162*>(hi)[i * 2]     = hp0;
    reinterpret_cast<__nv_bfloat162*>(hi)[i * 2 + 1] = hp1;
    __nv_bfloat162 lp0, lp1;
    lp0.x = __float2bfloat16_rn(v.x - __bfloat162float(h0));
    lp0.y = __float2bfloat16_rn(v.y - __bfloat162float(h1));
    lp1.x = __float2bfloat16_rn(v.z - __bfloat162float(h2));
    lp1.y = __float2bfloat16_rn(v.w - __bfloat162float(h3));
    reinterpret_cast<__nv_bfloat162*>(lo)[i * 2]     = lp0;
    reinterpret_cast<__nv_bfloat162*>(lo)[i * 2 + 1] = lp1;
}

// ---------------------------------------------------------------------------
// Split + transpose: w[K,N] fp32 -> hi/lo[N,K] bf16.
// ---------------------------------------------------------------------------
__global__ void split_T_kernel(const float* __restrict__ w,
                               __nv_bfloat16* __restrict__ hi,
                               __nv_bfloat16* __restrict__ lo, int K, int N)
{
    __shared__ float t[32][33];
    int k0 = blockIdx.y * 32, n0 = blockIdx.x * 32;
    int tx = threadIdx.x, ty = threadIdx.y;   // blockDim (32, 8)
    #pragma unroll
    for (int r = 0; r < 4; r++)
        t[ty + 8 * r][tx] = w[(size_t)(k0 + ty + 8 * r) * N + n0 + tx];
    __syncthreads();
    #pragma unroll
    for (int r = 0; r < 4; r++) {
        int n = ty + 8 * r;
        float x = t[tx][n];
        __nv_bfloat16 h = __float2bfloat16_rn(x);
        float rem = x - __bfloat162float(h);
        size_t o = (size_t)(n0 + n) * K + k0 + tx;
        hi[o] = h;
        lo[o] = __float2bfloat16_rn(rem);
    }
}

// ---------------------------------------------------------------------------
// Split-bf16 GEMM via mma.sync (HMMA): C[M,N] = A[M,K] @ W[N,K]^T
// 3 passes: Ahi*Whi + Ahi*Wlo + Alo*Whi.
// 128x128 block tile, BK=64, double-buffered cp.async smem, 8 warps (2x4),
// warp tile 64x32 = 4x4 m16n8 tiles.  smem rows padded to 144B (conflict-free).
// ---------------------------------------------------------------------------
#define GEMM_BK      64
#define GEMM_ROWB    144                    // bytes per padded smem row (72 bf16)
#define GEMM_TILE_B  (128 * GEMM_ROWB)      // 18432 per A or B tile
#define GEMM_BUF_B   (2 * GEMM_TILE_B)      // A+B for one stage
#define GEMM_SMEM    (2 * GEMM_BUF_B)       // double-buffered: 73728

__global__ __launch_bounds__(256, 2)
void gemm_split_kernel(const __nv_bfloat16* __restrict__ Ahi,
                       const __nv_bfloat16* __restrict__ Alo,
                       const __nv_bfloat16* __restrict__ Whi,
                       const __nv_bfloat16* __restrict__ Wlo,
                       float* __restrict__ C, int M, int N, int K)
{
    extern __shared__ char smc[];
    const uint32_t sbase = smem_u32(smc);

    const int tid  = threadIdx.x;
    const int wid  = tid >> 5;
    const int lane = tid & 31;
    const int wm   = wid >> 2;              // 0..1  (64 rows each)
    const int wn   = wid & 3;               // 0..3  (32 cols each)
    const int m0   = blockIdx.y * 128;
    const int n0   = blockIdx.x * 128;

    const int nk = K >> 6;                  // 64-wide k tiles per pass
    const int T  = 3 * nk;
    const __nv_bfloat16* Ap[3] = {Ahi, Ahi, Alo};
    const __nv_bfloat16* Bp[3] = {Whi, Wlo, Whi};

    float acc[4][4][4];
    #pragma unroll
    for (int i = 0; i < 4; i++)
        #pragma unroll
        for (int j = 0; j < 4; j++)
            #pragma unroll
            for (int q = 0; q < 4; q++) acc[i][j][q] = 0.0f;

    // per-thread load coords: 8 chunks of 16B (4 for A, 4 for B)
    auto load_tile = [&](int it, int buf) {
        int p  = it / nk;
        int k0 = (it - p * nk) << 6;
        const __nv_bfloat16* A = Ap[p];
        const __nv_bfloat16* W = Bp[p];
        uint32_t sA = sbase + buf * GEMM_BUF_B;
        uint32_t sB = sA + GEMM_TILE_B;
        #pragma unroll
        for (int l = 0; l < 4; l++) {
            int c   = tid + l * 256;        // 0..1023
            int row = c >> 3;
            int ch  = c & 7;
            uint32_t so = row * GEMM_ROWB + ch * 16;
            CP_ASYNC16(sA + so, A + (size_t)(m0 + row) * K + k0 + ch * 8);
            CP_ASYNC16(sB + so, W + (size_t)(n0 + row) * K + k0 + ch * 8);
        }
        CP_COMMIT();
    };

    load_tile(0, 0);

    // ldmatrix base addresses (buffer 0)
    const uint32_t a_off = (uint32_t)(wm * 64 + (lane & 15)) * GEMM_ROWB
                         + (lane >> 4) * 16;
    const uint32_t b_off = GEMM_TILE_B
                         + (uint32_t)(wn * 32 + (lane & 7) + ((lane >> 4) & 1) * 8) * GEMM_ROWB
                         + ((lane >> 3) & 1) * 16;

    for (int it = 0; it < T; it++) {
        int cur = it & 1;
        if (it + 1 < T) {
            load_tile(it + 1, cur ^ 1);
            cp_wait<1>();
        } else {
            cp_wait<0>();
        }
        __syncthreads();

        uint32_t abase = sbase + cur * GEMM_BUF_B + a_off;
        uint32_t bbase = sbase + cur * GEMM_BUF_B + b_off;

        #pragma unroll
        for (int ks = 0; ks < 4; ks++) {
            uint32_t af[4][4];
            #pragma unroll
            for (int mt = 0; mt < 4; mt++)
                LDSM4(af[mt], abase + mt * (16 * GEMM_ROWB) + ks * 32);
            uint32_t bf2[2][4];
            #pragma unroll
            for (int nt2 = 0; nt2 < 2; nt2++)
                LDSM4(bf2[nt2], bbase + nt2 * (16 * GEMM_ROWB) + ks * 32);
            #pragma unroll
            for (int mt = 0; mt < 4; mt++)
                #pragma unroll
                for (int nt = 0; nt < 4; nt++)
                    MMA16816(acc[mt][nt], af[mt],
                             bf2[nt >> 1][(nt & 1) * 2],
                             bf2[nt >> 1][(nt & 1) * 2 + 1]);
        }
        __syncthreads();   // done reading 'cur' before it gets overwritten
    }

    // epilogue
    #pragma unroll
    for (int mt = 0; mt < 4; mt++) {
        int row0 = m0 + wm * 64 + mt * 16 + (lane >> 2);
        #pragma unroll
        for (int nt = 0; nt < 4; nt++) {
            int col = n0 + wn * 32 + nt * 8 + 2 * (lane & 3);
            float2 v0 = make_float2(acc[mt][nt][0], acc[mt][nt][1]);
            float2 v1 = make_float2(acc[mt][nt][2], acc[mt][nt][3]);
            *reinterpret_cast<float2*>(&C[(size_t)row0 * N + col])       = v0;
            *reinterpret_cast<float2*>(&C[(size_t)(row0 + 8) * N + col]) = v1;
        }
    }
}

// ---------------------------------------------------------------------------
// RoPE (in-place on g_q, g_k).
// ---------------------------------------------------------------------------
__global__ void rope_kernel(const int* __restrict__ pos)
{
    int idx = blockIdx.x * blockDim.x + threadIdx.x;
    const int nq = M_TOK * H_  * 64;
    const int nk = M_TOK * KH_ * 64;
    float* base;
    int t, dp;
    if (idx < nq) {
        dp = idx & 63; int r = idx >> 6;
        int h = r & 31; t = r >> 5;
        base = &g_q[((size_t)t * H_ + h) * D_];
    } else {
        idx -= nq;
        if (idx >= nk) return;
        dp = idx & 63; int r = idx >> 6;
        int h = r & 7;  t = r >> 3;
        base = &g_k[((size_t)t * KH_ + h) * D_];
    }
    float p   = (float)pos[t];
    float ang = p * exp2f((float)dp * (-19.931568569324174f / 64.0f));
    float sn, cs;
    sincosf(ang, &sn, &cs);
    float x1 = base[dp], x2 = base[dp + 64];
    base[dp]      = x1 * cs - x2 * sn;
    base[dp + 64] = x2 * cs + x1 * sn;
}

// ---------------------------------------------------------------------------
// Flash attention, sliding window causal, GQA. (unchanged from R1)
// ---------------------------------------------------------------------------
#define ATT_SMEM_FLOATS (64*129 + 64*129 + 64*132 + 64*68)
#define ATT_SMEM_BYTES  (ATT_SMEM_FLOATS * 4)

__global__ __launch_bounds__(256, 1)
void attn_kernel()
{
    extern __shared__ float sm[];
    float* Qs = sm;
    float* Ks = Qs + 64 * 129;
    float* Vs = Ks + 64 * 129;
    float* Ps = Vs + 64 * 132;

    const int tid = threadIdx.x;
    const int tx  = tid & 15;
    const int ty  = tid >> 4;
    const int tm0 = ty * 4;
    const int tn0 = tx * 4;
    const int i0  = blockIdx.x * 64;
    const int h   = blockIdx.y;
    const int b   = blockIdx.z;
    const int kh  = h >> 2;

    const float qscale = 0.08838834764831845f;
    for (int i = tid; i < 64 * 128; i += 256) {
        int r = i >> 7, d = i & 127;
        Qs[r * 129 + d] =
            g_q[(((size_t)(b * S_ + i0 + r)) * H_ + h) * D_ + d] * qscale;
    }

    float acc[4][8];
    #pragma unroll
    for (int i = 0; i < 4; i++)
        #pragma unroll
        for (int j = 0; j < 8; j++) acc[i][j] = 0.0f;
    float rm[4] = {-1e30f, -1e30f, -1e30f, -1e30f};
    float rl[4] = {0.f, 0.f, 0.f, 0.f};

    int lo  = i0 - WIN_ + 1; if (lo < 0) lo = 0;
    int jt0 = lo >> 6;
    int jt1 = i0 >> 6;

    for (int jt = jt0; jt <= jt1; jt++) {
        int j0 = jt << 6;
        __syncthreads();
        for (int i = tid; i < 64 * 128; i += 256) {
            int r = i >> 7, d = i & 127;
            size_t tok = (size_t)(b * S_ + j0 + r);
            Ks[r * 129 + d] = g_k[(tok * KH_ + kh) * D_ + d];
            Vs[r * 132 + d] = g_v[(tok * KH_ + kh) * D_ + d];
        }
        __syncthreads();

        float s[4][4];
        #pragma unroll
        for (int i = 0; i < 4; i++)
            #pragma unroll
            for (int j = 0; j < 4; j++) s[i][j] = 0.0f;

        #pragma unroll 4
        for (int d = 0; d < 128; d++) {
            float a0 = Qs[(tm0 + 0) * 129 + d];
            float a1 = Qs[(tm0 + 1) * 129 + d];
            float a2 = Qs[(tm0 + 2) * 129 + d];
            float a3 = Qs[(tm0 + 3) * 129 + d];
            float b0 = Ks[(tn0 + 0) * 129 + d];
            float b1 = Ks[(tn0 + 1) * 129 + d];
            float b2 = Ks[(tn0 + 2) * 129 + d];
            float b3 = Ks[(tn0 + 3) * 129 + d];
            s[0][0] = fmaf(a0, b0, s[0][0]); s[0][1] = fmaf(a0, b1, s[0][1]);
            s[0][2] = fmaf(a0, b2, s[0][2]); s[0][3] = fmaf(a0, b3, s[0][3]);
            s[1][0] = fmaf(a1, b0, s[1][0]); s[1][1] = fmaf(a1, b1, s[1][1]);
            s[1][2] = fmaf(a1, b2, s[1][2]); s[1][3] = fmaf(a1, b3, s[1][3]);
            s[2][0] = fmaf(a2, b0, s[2][0]); s[2][1] = fmaf(a2, b1, s[2][1]);
            s[2][2] = fmaf(a2, b2, s[2][2]); s[2][3] = fmaf(a2, b3, s[2][3]);
            s[3][0] = fmaf(a3, b0, s[3][0]); s[3][1] = fmaf(a3, b1, s[3][1]);
            s[3][2] = fmaf(a3, b2, s[3][2]); s[3][3] = fmaf(a3, b3, s[3][3]);
        }

        #pragma unroll
        for (int i = 0; i < 4; i++) {
            int qq = i0 + tm0 + i;
            float tmax = -1e30f;
            #pragma unroll
            for (int j = 0; j < 4; j++) {
                int kj = j0 + tn0 + j;
                if (kj > qq || (qq - kj) >= WIN_) s[i][j] = -1e30f;
                tmax = fmaxf(tmax, s[i][j]);
            }
            tmax = fmaxf(tmax, __shfl_xor_sync(0xffffffffu, tmax, 8));
            tmax = fmaxf(tmax, __shfl_xor_sync(0xffffffffu, tmax, 4));
            tmax = fmaxf(tmax, __shfl_xor_sync(0xffffffffu, tmax, 2));
            tmax = fmaxf(tmax, __shfl_xor_sync(0xffffffffu, tmax, 1));
            float mnew = fmaxf(rm[i], tmax);
            float scl  = __expf(rm[i] - mnew);
            float rs = 0.0f;
            #pragma unroll
            for (int j = 0; j < 4; j++) {
                float p = __expf(s[i][j] - mnew);
                s[i][j] = p;
                rs += p;
            }
            rs += __shfl_xor_sync(0xffffffffu, rs, 8);
            rs += __shfl_xor_sync(0xffffffffu, rs, 4);
            rs += __shfl_xor_sync(0xffffffffu, rs, 2);
            rs += __shfl_xor_sync(0xffffffffu, rs, 1);
            rl[i] = rl[i] * scl + rs;
            rm[i] = mnew;
            #pragma unroll
            for (int j = 0; j < 8; j++) acc[i][j] *= scl;
            #pragma unroll
            for (int j = 0; j < 4; j++)
                Ps[(tm0 + i) * 68 + tn0 + j] = s[i][j];
        }
        __syncthreads();

        #pragma unroll 2
        for (int kk = 0; kk < 64; kk++) {
            float p0 = Ps[(tm0 + 0) * 68 + kk];
            float p1 = Ps[(tm0 + 1) * 68 + kk];
            float p2 = Ps[(tm0 + 2) * 68 + kk];
            float p3 = Ps[(tm0 + 3) * 68 + kk];
            float4 v0 = *reinterpret_cast<const float4*>(&Vs[kk * 132 + tx * 8]);
            float4 v1 = *reinterpret_cast<const float4*>(&Vs[kk * 132 + tx * 8 + 4]);
            float v[8] = {v0.x, v0.y, v0.z, v0.w, v1.x, v1.y, v1.z, v1.w};
            #pragma unroll
            for (int j = 0; j < 8; j++) {
                acc[0][j] = fmaf(p0, v[j], acc[0][j]);
                acc[1][j] = fmaf(p1, v[j], acc[1][j]);
                acc[2][j] = fmaf(p2, v[j], acc[2][j]);
                acc[3][j] = fmaf(p3, v[j], acc[3][j]);
            }
        }
    }

    #pragma unroll
    for (int i = 0; i < 4; i++) {
        float inv = 1.0f / rl[i];
        size_t tok = (size_t)(b * S_ + i0 + tm0 + i);
        float* dst = &g_ao[(tok * H_ + h) * D_ + tx * 8];
        float4 o0 = make_float4(acc[i][0] * inv, acc[i][1] * inv,
                                acc[i][2] * inv, acc[i][3] * inv);
        float4 o1 = make_float4(acc[i][4] * inv, acc[i][5] * inv,
                                acc[i][6] * inv, acc[i][7] * inv);
        *reinterpret_cast<float4*>(dst)     = o0;
        *reinterpret_cast<float4*>(dst + 4) = o1;
    }
}

// ---------------------------------------------------------------------------
extern "C" void kernel_launch(void* const* d_in, const int* in_sizes, int n_in,
                              void* d_out, int out_size)
{
    const float* hidden = (const float*)d_in[0];  // [2,2048,4096]
    const int*   pos    = (const int*)  d_in[1];  // [2,2048]
    const float* wq     = (const float*)d_in[2];  // [4096,4096]
    const float* wk     = (const float*)d_in[3];  // [4096,1024]
    const float* wv     = (const float*)d_in[4];  // [4096,1024]
    const float* wo     = (const float*)d_in[5];  // [4096,4096]
    float* out = (float*)d_out;                   // [2,2048,4096]

    float *gq, *gk, *gv, *gao;
    __nv_bfloat16 *ahi, *alo, *wqh, *wql, *wkh, *wkl, *wvh, *wvl, *woh, *wol;
    cudaGetSymbolAddress((void**)&gq,  g_q);
    cudaGetSymbolAddress((void**)&gk,  g_k);
    cudaGetSymbolAddress((void**)&gv,  g_v);
    cudaGetSymbolAddress((void**)&gao, g_ao);
    cudaGetSymbolAddress((void**)&ahi, g_Ahi);
    cudaGetSymbolAddress((void**)&alo, g_Alo);
    cudaGetSymbolAddress((void**)&wqh, g_Wqhi);
    cudaGetSymbolAddress((void**)&wql, g_Wqlo);
    cudaGetSymbolAddress((void**)&wkh, g_Wkhi);
    cudaGetSymbolAddress((void**)&wkl, g_Wklo);
    cudaGetSymbolAddress((void**)&wvh, g_Wvhi);
    cudaGetSymbolAddress((void**)&wvl, g_Wvlo);
    cudaGetSymbolAddress((void**)&woh, g_Wohi);
    cudaGetSymbolAddress((void**)&wol, g_Wolo);

    cudaFuncSetAttribute(gemm_split_kernel,
                         cudaFuncAttributeMaxDynamicSharedMemorySize, GEMM_SMEM);
    cudaFuncSetAttribute(attn_kernel,
                         cudaFuncAttributeMaxDynamicSharedMemorySize, ATT_SMEM_BYTES);

    // ---- split inputs into bf16 hi/lo ----
    split_kernel<<<(M_TOK * HID_ / 4 + 255) / 256, 256>>>(hidden, ahi, alo,
                                                          M_TOK * HID_ / 4);
    split_T_kernel<<<dim3((H_*D_)/32,  HID_/32), dim3(32, 8)>>>(wq, wqh, wql, HID_, H_*D_);
    split_T_kernel<<<dim3((KH_*D_)/32, HID_/32), dim3(32, 8)>>>(wk, wkh, wkl, HID_, KH_*D_);
    split_T_kernel<<<dim3((KH_*D_)/32, HID_/32), dim3(32, 8)>>>(wv, wvh, wvl, HID_, KH_*D_);
    split_T_kernel<<<dim3(HID_/32, (H_*D_)/32), dim3(32, 8)>>>(wo, woh, wol, H_*D_, HID_);

    // ---- QKV projections (HMMA split-bf16) ----
    gemm_split_kernel<<<dim3((H_*D_)/128,  M_TOK/128), 256, GEMM_SMEM>>>(
        ahi, alo, wqh, wql, gq, M_TOK, H_*D_,  HID_);
    gemm_split_kernel<<<dim3((KH_*D_)/128, M_TOK/128), 256, GEMM_SMEM>>>(
        ahi, alo, wkh, wkl, gk, M_TOK, KH_*D_, HID_);
    gemm_split_kernel<<<dim3((KH_*D_)/128, M_TOK/128), 256, GEMM_SMEM>>>(
        ahi, alo, wvh, wvl, gv, M_TOK, KH_*D_, HID_);

    // ---- RoPE ----
    {
        int total = M_TOK * H_ * 64 + M_TOK * KH_ * 64;
        rope_kernel<<<(total + 255) / 256, 256>>>(pos);
    }

    // ---- Attention ----
    attn_kernel<<<dim3(S_ / 64, H_, B_), 256, ATT_SMEM_BYTES>>>();

    // ---- Output projection ----
    split_kernel<<<(M_TOK * HID_ / 4 + 255) / 256, 256>>>(gao, ahi, alo,
                                                          M_TOK * HID_ / 4);
    gemm_split_kernel<<<dim3(HID_/128, M_TOK/128), 256, GEMM_SMEM>>>(
        ahi, alo, woh, wol, out, M_TOK, HID_, H_*D_);
}

// round 4
// speedup vs baseline: 2.8278x; 1.5076x over previous
#include <cuda_runtime.h>
#include <cuda_bf16.h>
#include <math.h>
#include <stdint.h>
#include <string.h>

#define B_   2
#define S_   2048
#define HID_ 4096
#define H_   32
#define KH_  8
#define D_   128
#define WIN_ 1024
#define M_TOK (B_*S_)   // 4096 tokens
#define NQKV (H_*D_ + 2*KH_*D_)   // 6144

// ---------------------------------------------------------------------------
// Scratch (__device__ globals; no allocation allowed)
// ---------------------------------------------------------------------------
__device__ float g_qkv[M_TOK * NQKV];            // fused QKV output (fp32)
__device__ float g_ao [M_TOK * H_ * D_];         // attention output (fp32)

__device__ __nv_bfloat16 g_Ahi[M_TOK * HID_];    // activation splits
__device__ __nv_bfloat16 g_Alo[M_TOK * HID_];
__device__ __nv_bfloat16 g_Wqkvhi[NQKV * HID_];  // fused QKV weights [N][K]
__device__ __nv_bfloat16 g_Wqkvlo[NQKV * HID_];
__device__ __nv_bfloat16 g_Wohi[HID_ * (H_*D_)];
__device__ __nv_bfloat16 g_Wolo[HID_ * (H_*D_)];

// attention operands, bf16 hi/lo
__device__ __nv_bfloat16 g_qh[M_TOK * H_  * D_]; // [tok][h][d]  (scaled, log2 domain)
__device__ __nv_bfloat16 g_ql[M_TOK * H_  * D_];
__device__ __nv_bfloat16 g_kh[M_TOK * KH_ * D_]; // [tok][kh][d]
__device__ __nv_bfloat16 g_kl[M_TOK * KH_ * D_];
__device__ __nv_bfloat16 g_vh[M_TOK * KH_ * D_];
__device__ __nv_bfloat16 g_vl[M_TOK * KH_ * D_];

// ---------------------------------------------------------------------------
// PTX helpers (family-target safe)
// ---------------------------------------------------------------------------
__device__ __forceinline__ uint32_t smem_u32(const void* p) {
    uint32_t a;
    asm("{ .reg .u64 t; cvta.to.shared.u64 t, %1; cvt.u32.u64 %0, t; }"
        : "=r"(a) : "l"(p));
    return a;
}
#define CP_ASYNC16(saddr, gaddr) \
    asm volatile("cp.async.cg.shared.global [%0], [%1], 16;" \
                 :: "r"(saddr), "l"(gaddr))
#define CP_COMMIT() asm volatile("cp.async.commit_group;" ::: "memory")
template <int N>
__device__ __forceinline__ void cp_wait() {
    asm volatile("cp.async.wait_group %0;" :: "n"(N) : "memory");
}
#define LDSM4(r, a) \
    asm volatile("ldmatrix.sync.aligned.m8n8.x4.shared.b16 {%0,%1,%2,%3}, [%4];" \
                 : "=r"((r)[0]), "=r"((r)[1]), "=r"((r)[2]), "=r"((r)[3]) : "r"(a))
#define LDSM4T(r, a) \
    asm volatile("ldmatrix.sync.aligned.m8n8.x4.trans.shared.b16 {%0,%1,%2,%3}, [%4];" \
                 : "=r"((r)[0]), "=r"((r)[1]), "=r"((r)[2]), "=r"((r)[3]) : "r"(a))
#define MMA16816(c, a, b0v, b1v) \
    asm volatile("mma.sync.aligned.m16n8k16.row.col.f32.bf16.bf16.f32 " \
                 "{%0,%1,%2,%3}, {%4,%5,%6,%7}, {%8,%9}, {%0,%1,%2,%3};" \
                 : "+f"((c)[0]), "+f"((c)[1]), "+f"((c)[2]), "+f"((c)[3]) \
                 : "r"((a)[0]), "r"((a)[1]), "r"((a)[2]), "r"((a)[3]), \
                   "r"(b0v), "r"(b1v))

__device__ __forceinline__ float ex2(float x) {
    float y;
    asm("ex2.approx.ftz.f32 %0, %1;" : "=f"(y) : "f"(x));
    return y;
}
__device__ __forceinline__ uint32_t pack_bf2(float x, float y) {
    __nv_bfloat162 h = __floats2bfloat162_rn(x, y);
    uint32_t u;
    memcpy(&u, &h, 4);
    return u;
}

// ---------------------------------------------------------------------------
// Split fp32 -> (hi, lo) bf16, same layout. n must be /4.
// ---------------------------------------------------------------------------
__global__ void split_kernel(const float* __restrict__ in,
                             __nv_bfloat16* __restrict__ hi,
                             __nv_bfloat16* __restrict__ lo, int n4)
{
    int i = blockIdx.x * blockDim.x + threadIdx.x;
    if (i >= n4) return;
    float4 v = reinterpret_cast<const float4*>(in)[i];
    __nv_bfloat16 h0 = __float2bfloat16_rn(v.x);
    __nv_bfloat16 h1 = __float2bfloat16_rn(v.y);
    __nv_bfloat16 h2 = __float2bfloat16_rn(v.z);
    __nv_bfloat16 h3 = __float2bfloat16_rn(v.w);
    __nv_bfloat162 hp0; hp0.x = h0; hp0.y = h1;
    __nv_bfloat162 hp1; hp1.x = h2; hp1.y = h3;
    reinterpret_cast<__nv_bfloat162*>(hi)[i * 2]     = hp0;
    reinterpret_cast<__nv_bfloat162*>(hi)[i * 2 + 1] = hp1;
    __nv_bfloat162 lp0, lp1;
    lp0.x = __float2bfloat16_rn(v.x - __bfloat162float(h0));
    lp0.y = __float2bfloat16_rn(v.y - __bfloat162float(h1));
    lp1.x = __float2bfloat16_rn(v.z - __bfloat162float(h2));
    lp1.y = __float2bfloat16_rn(v.w - __bfloat162float(h3));
    reinterpret_cast<__nv_bfloat162*>(lo)[i * 2]     = lp0;
    reinterpret_cast<__nv_bfloat162*>(lo)[i * 2 + 1] = lp1;
}

// ---------------------------------------------------------------------------
// Split + transpose: w[K,N] fp32 -> hi/lo[N,K] bf16.
// ---------------------------------------------------------------------------
__global__ void split_T_kernel(const float* __restrict__ w,
                               __nv_bfloat16* __restrict__ hi,
                               __nv_bfloat16* __restrict__ lo, int K, int N)
{
    __shared__ float t[32][33];
    int k0 = blockIdx.y * 32, n0 = blockIdx.x * 32;
    int tx = threadIdx.x, ty = threadIdx.y;
    #pragma unroll
    for (int r = 0; r < 4; r++)
        t[ty + 8 * r][tx] = w[(size_t)(k0 + ty + 8 * r) * N + n0 + tx];
    __syncthreads();
    #pragma unroll
    for (int r = 0; r < 4; r++) {
        int n = ty + 8 * r;
        float x = t[tx][n];
        __nv_bfloat16 h = __float2bfloat16_rn(x);
        float rem = x - __bfloat162float(h);
        size_t o = (size_t)(n0 + n) * K + k0 + tx;
        hi[o] = h;
        lo[o] = __float2bfloat16_rn(rem);
    }
}

// ---------------------------------------------------------------------------
// Split-bf16 GEMM via mma.sync (HMMA): C[M,N] = A[M,K] @ W[N,K]^T (3-term)
// ---------------------------------------------------------------------------
#define GEMM_ROWB    144
#define GEMM_TILE_B  (128 * GEMM_ROWB)
#define GEMM_BUF_B   (2 * GEMM_TILE_B)
#define GEMM_SMEM    (2 * GEMM_BUF_B)

__global__ __launch_bounds__(256, 2)
void gemm_split_kernel(const __nv_bfloat16* __restrict__ Ahi,
                       const __nv_bfloat16* __restrict__ Alo,
                       const __nv_bfloat16* __restrict__ Whi,
                       const __nv_bfloat16* __restrict__ Wlo,
                       float* __restrict__ C, int M, int N, int K)
{
    extern __shared__ char smc[];
    const uint32_t sbase = smem_u32(smc);

    const int tid  = threadIdx.x;
    const int wid  = tid >> 5;
    const int lane = tid & 31;
    const int wm   = wid >> 2;
    const int wn   = wid & 3;
    const int m0   = blockIdx.y * 128;
    const int n0   = blockIdx.x * 128;

    const int nk = K >> 6;
    const int T  = 3 * nk;
    const __nv_bfloat16* Ap[3] = {Ahi, Ahi, Alo};
    const __nv_bfloat16* Bp[3] = {Whi, Wlo, Whi};

    float acc[4][4][4];
    #pragma unroll
    for (int i = 0; i < 4; i++)
        #pragma unroll
        for (int j = 0; j < 4; j++)
            #pragma unroll
            for (int q = 0; q < 4; q++) acc[i][j][q] = 0.0f;

    auto load_tile = [&](int it, int buf) {
        int p  = it / nk;
        int k0 = (it - p * nk) << 6;
        const __nv_bfloat16* A = Ap[p];
        const __nv_bfloat16* W = Bp[p];
        uint32_t sA = sbase + buf * GEMM_BUF_B;
        uint32_t sB = sA + GEMM_TILE_B;
        #pragma unroll
        for (int l = 0; l < 4; l++) {
            int c   = tid + l * 256;
            int row = c >> 3;
            int ch  = c & 7;
            uint32_t so = row * GEMM_ROWB + ch * 16;
            CP_ASYNC16(sA + so, A + (size_t)(m0 + row) * K + k0 + ch * 8);
            CP_ASYNC16(sB + so, W + (size_t)(n0 + row) * K + k0 + ch * 8);
        }
        CP_COMMIT();
    };

    load_tile(0, 0);

    const uint32_t a_off = (uint32_t)(wm * 64 + (lane & 15)) * GEMM_ROWB
                         + (lane >> 4) * 16;
    const uint32_t b_off = GEMM_TILE_B
                         + (uint32_t)(wn * 32 + (lane & 7) + ((lane >> 4) & 1) * 8) * GEMM_ROWB
                         + ((lane >> 3) & 1) * 16;

    for (int it = 0; it < T; it++) {
        int cur = it & 1;
        if (it + 1 < T) {
            load_tile(it + 1, cur ^ 1);
            cp_wait<1>();
        } else {
            cp_wait<0>();
        }
        __syncthreads();

        uint32_t abase = sbase + cur * GEMM_BUF_B + a_off;
        uint32_t bbase = sbase + cur * GEMM_BUF_B + b_off;

        #pragma unroll
        for (int ks = 0; ks < 4; ks++) {
            uint32_t af[4][4];
            #pragma unroll
            for (int mt = 0; mt < 4; mt++)
                LDSM4(af[mt], abase + mt * (16 * GEMM_ROWB) + ks * 32);
            uint32_t bf2[2][4];
            #pragma unroll
            for (int nt2 = 0; nt2 < 2; nt2++)
                LDSM4(bf2[nt2], bbase + nt2 * (16 * GEMM_ROWB) + ks * 32);
            #pragma unroll
            for (int mt = 0; mt < 4; mt++)
                #pragma unroll
                for (int nt = 0; nt < 4; nt++)
                    MMA16816(acc[mt][nt], af[mt],
                             bf2[nt >> 1][(nt & 1) * 2],
                             bf2[nt >> 1][(nt & 1) * 2 + 1]);
        }
        __syncthreads();
    }

    #pragma unroll
    for (int mt = 0; mt < 4; mt++) {
        int row0 = m0 + wm * 64 + mt * 16 + (lane >> 2);
        #pragma unroll
        for (int nt = 0; nt < 4; nt++) {
            int col = n0 + wn * 32 + nt * 8 + 2 * (lane & 3);
            float2 v0 = make_float2(acc[mt][nt][0], acc[mt][nt][1]);
            float2 v1 = make_float2(acc[mt][nt][2], acc[mt][nt][3]);
            *reinterpret_cast<float2*>(&C[(size_t)row0 * N + col])       = v0;
            *reinterpret_cast<float2*>(&C[(size_t)(row0 + 8) * N + col]) = v1;
        }
    }
}

// ---------------------------------------------------------------------------
// RoPE + split from fused g_qkv:
//   Q -> rope, * (1/sqrt(D))*log2(e), split -> g_qh/g_ql  [tok][h][d]
//   K -> rope, split -> g_kh/g_kl  [tok][kh][d]
//   V -> split -> g_vh/g_vl  [tok][kh][d]
// ---------------------------------------------------------------------------
__device__ __forceinline__ void split_store(__nv_bfloat16* hi, __nv_bfloat16* lo,
                                            size_t o, float x) {
    __nv_bfloat16 h = __float2bfloat16_rn(x);
    hi[o] = h;
    lo[o] = __float2bfloat16_rn(x - __bfloat162float(h));
}

__global__ void rope_split_kernel(const int* __restrict__ pos)
{
    const float QS = 0.08838834764831845f * 1.4426950408889634f; // 1/sqrt(128)*log2(e)
    int idx = blockIdx.x * blockDim.x + threadIdx.x;
    const int nq = M_TOK * H_  * 64;
    const int nk = M_TOK * KH_ * 64;
    const int nv = M_TOK * KH_ * 64;

    if (idx < nq) {
        int dp = idx & 63; int r = idx >> 6;
        int hh = r & 31;   int t = r >> 5;
        const float* base = g_qkv + (size_t)t * NQKV + hh * D_;
        float p   = (float)pos[t];
        float ang = p * exp2f((float)dp * (-19.931568569324174f / 64.0f));
        float sn, cs; sincosf(ang, &sn, &cs);
        float x1 = base[dp], x2 = base[dp + 64];
        float y1 = (x1 * cs - x2 * sn) * QS;
        float y2 = (x2 * cs + x1 * sn) * QS;
        size_t o = ((size_t)t * H_ + hh) * D_;
        split_store(g_qh, g_ql, o + dp,      y1);
        split_store(g_qh, g_ql, o + dp + 64, y2);
        return;
    }
    idx -= nq;
    if (idx < nk) {
        int dp = idx & 63; int r = idx >> 6;
        int hh = r & 7;    int t = r >> 3;
        const float* base = g_qkv + (size_t)t * NQKV + H_*D_ + hh * D_;
        float p   = (float)pos[t];
        float ang = p * exp2f((float)dp * (-19.931568569324174f / 64.0f));
        float sn, cs; sincosf(ang, &sn, &cs);
        float x1 = base[dp], x2 = base[dp + 64];
        float y1 = x1 * cs - x2 * sn;
        float y2 = x2 * cs + x1 * sn;
        size_t o = ((size_t)t * KH_ + hh) * D_;
        split_store(g_kh, g_kl, o + dp,      y1);
        split_store(g_kh, g_kl, o + dp + 64, y2);
        return;
    }
    idx -= nk;
    if (idx >= nv) return;
    {
        int dp = idx & 63; int r = idx >> 6;
        int hh = r & 7;    int t = r >> 3;
        const float* base = g_qkv + (size_t)t * NQKV + H_*D_ + KH_*D_ + hh * D_;
        size_t o = ((size_t)t * KH_ + hh) * D_;
        split_store(g_vh, g_vl, o + dp,      base[dp]);
        split_store(g_vh, g_vl, o + dp + 64, base[dp + 64]);
    }
}

// ---------------------------------------------------------------------------
// HMMA flash attention, split-bf16 3-term QK and PV.
// CTA: 128 Q rows, 8 warps (16 rows each). K-tile 64 tokens.
// Smem: double-buffered K/V hi/lo stages; Q staged once at start.
// ---------------------------------------------------------------------------
#define AT_STRIDE 272
#define AT_SUBT   (64 * AT_STRIDE)   // 17408
#define AT_STAGE  (4 * AT_SUBT)      // 69632
#define AT_SMEM   (2 * AT_STAGE)     // 139264
#define NEGINF    (-1e30f)
#define MFLOOR    (-1e4f)

__global__ __launch_bounds__(256, 1)
void attn_mma_kernel()
{
    extern __shared__ char smraw[];
    const uint32_t sb = smem_u32(smraw);
    const int tid = threadIdx.x, wid = tid >> 5, lane = tid & 31;
    const int q0 = blockIdx.x * 128;
    const int h  = blockIdx.y;
    const int b  = blockIdx.z;
    const int kh = h >> 2;

    // ---- stage Q (hi, lo) ----
    #pragma unroll
    for (int l = 0; l < 16; l++) {
        int c    = tid + l * 256;           // 0..4095
        int half = c >> 11;                 // 0 hi, 1 lo
        int rem  = c & 2047;
        int row  = rem >> 4, ch = rem & 15;
        const __nv_bfloat16* src = half ? g_ql : g_qh;
        uint32_t sa = sb + half * (128 * AT_STRIDE) + row * AT_STRIDE + ch * 16;
        CP_ASYNC16(sa, src + ((size_t)(b * S_ + q0 + row) * H_ + h) * D_ + ch * 8);
    }
    CP_COMMIT();
    cp_wait<0>();
    __syncthreads();

    // Q fragments (resident)
    uint32_t qfh[8][4], qfl[8][4];
    {
        uint32_t qa = sb + (uint32_t)(wid * 16 + (lane & 15)) * AT_STRIDE
                    + ((lane >> 4) & 1) * 16;
        #pragma unroll
        for (int ks = 0; ks < 8; ks++) {
            LDSM4(qfh[ks], qa + ks * 32);
            LDSM4(qfl[ks], qa + 128 * AT_STRIDE + ks * 32);
        }
    }
    __syncthreads();   // Q smem free for K/V stages

    // O accum + softmax state
    float o[16][4];
    #pragma unroll
    for (int i = 0; i < 16; i++)
        #pragma unroll
        for (int j = 0; j < 4; j++) o[i][j] = 0.0f;
    float m0 = MFLOOR, m1 = MFLOOR, l0 = 0.0f, l1 = 0.0f;

    int lotok = q0 - WIN_ + 1; if (lotok < 0) lotok = 0;
    const int jt0 = lotok >> 6;
    const int jt1 = (q0 + 127) >> 6;

    auto load_kv = [&](int jt, int stg) {
        int j0 = jt << 6;
        const __nv_bfloat16* srcs[4] = {g_kh, g_kl, g_vh, g_vl};
        #pragma unroll
        for (int l = 0; l < 16; l++) {
            int c   = tid + l * 256;        // 0..4095
            int sub = c >> 10;
            int rem = c & 1023;
            int row = rem >> 4, ch = rem & 15;
            uint32_t sa = sb + stg * AT_STAGE + sub * AT_SUBT
                        + row * AT_STRIDE + ch * 16;
            CP_ASYNC16(sa, srcs[sub] +
                       ((size_t)(b * S_ + j0 + row) * KH_ + kh) * D_ + ch * 8);
        }
        CP_COMMIT();
    };

    load_kv(jt0, 0);

    // ldmatrix lane addressing
    const uint32_t kb_off = (uint32_t)((lane & 7) + ((lane >> 4) & 1) * 8) * AT_STRIDE
                          + ((lane >> 3) & 1) * 16;
    const uint32_t vt_off = (uint32_t)((lane & 7) + ((lane >> 3) & 1) * 8) * AT_STRIDE
                          + (lane >> 4) * 16;   // (lane>>4)*8 cols * 2B

    const int rbase0 = q0 + wid * 16 + (lane >> 2);

    for (int jt = jt0; jt <= jt1; jt++) {
        const int cur = (jt - jt0) & 1;
        const int j0  = jt << 6;
        cp_wait<0>();
        __syncthreads();
        if (jt + 1 <= jt1) load_kv(jt + 1, cur ^ 1);

        const uint32_t stgb = sb + cur * AT_STAGE;

        // ---- S = Q K^T (3-term) ----
        float s[8][4];
        #pragma unroll
        for (int i = 0; i < 8; i++)
            #pragma unroll
            for (int j = 0; j < 4; j++) s[i][j] = 0.0f;

        #pragma unroll
        for (int ks = 0; ks < 8; ks++) {
            #pragma unroll
            for (int nt2 = 0; nt2 < 4; nt2++) {
                uint32_t a = stgb + kb_off + (uint32_t)nt2 * (16 * AT_STRIDE) + ks * 32;
                uint32_t kf[4];
                LDSM4(kf, a);               // K hi
                MMA16816(s[2*nt2],   qfh[ks], kf[0], kf[1]);
                MMA16816(s[2*nt2+1], qfh[ks], kf[2], kf[3]);
                MMA16816(s[2*nt2],   qfl[ks], kf[0], kf[1]);
                MMA16816(s[2*nt2+1], qfl[ks], kf[2], kf[3]);
                LDSM4(kf, a + AT_SUBT);     // K lo
                MMA16816(s[2*nt2],   qfh[ks], kf[0], kf[1]);
                MMA16816(s[2*nt2+1], qfh[ks], kf[2], kf[3]);
            }
        }

        // ---- mask ----
        const bool needM = (j0 + 63 > q0) || ((q0 + 127 - j0) >= WIN_);
        if (needM) {
            #pragma unroll
            for (int nt = 0; nt < 8; nt++) {
                int colb = j0 + nt * 8 + 2 * (lane & 3);
                #pragma unroll
                for (int e = 0; e < 4; e++) {
                    int col = colb + (e & 1);
                    int row = rbase0 + (e >> 1) * 8;
                    if (col > row || (row - col) >= WIN_) s[nt][e] = NEGINF;
                }
            }
        }

        // ---- online softmax (log2 domain) ----
        float t0 = NEGINF, t1 = NEGINF;
        #pragma unroll
        for (int nt = 0; nt < 8; nt++) {
            t0 = fmaxf(t0, fmaxf(s[nt][0], s[nt][1]));
            t1 = fmaxf(t1, fmaxf(s[nt][2], s[nt][3]));
        }
        t0 = fmaxf(t0, __shfl_xor_sync(0xffffffffu, t0, 1));
        t0 = fmaxf(t0, __shfl_xor_sync(0xffffffffu, t0, 2));
        t1 = fmaxf(t1, __shfl_xor_sync(0xffffffffu, t1, 1));
        t1 = fmaxf(t1, __shfl_xor_sync(0xffffffffu, t1, 2));
        float n0 = fmaxf(fmaxf(m0, t0), MFLOOR);
        float n1 = fmaxf(fmaxf(m1, t1), MFLOOR);
        float sc0 = ex2(m0 - n0);
        float sc1 = ex2(m1 - n1);
        float rs0 = 0.0f, rs1 = 0.0f;
        #pragma unroll
        for (int nt = 0; nt < 8; nt++) {
            s[nt][0] = ex2(s[nt][0] - n0); rs0 += s[nt][0];
            s[nt][1] = ex2(s[nt][1] - n0); rs0 += s[nt][1];
            s[nt][2] = ex2(s[nt][2] - n1); rs1 += s[nt][2];
            s[nt][3] = ex2(s[nt][3] - n1); rs1 += s[nt][3];
        }
        rs0 += __shfl_xor_sync(0xffffffffu, rs0, 1);
        rs0 += __shfl_xor_sync(0xffffffffu, rs0, 2);
        rs1 += __shfl_xor_sync(0xffffffffu, rs1, 1);
        rs1 += __shfl_xor_sync(0xffffffffu, rs1, 2);
        l0 = l0 * sc0 + rs0;
        l1 = l1 * sc1 + rs1;
        m0 = n0; m1 = n1;
        #pragma unroll
        for (int nt = 0; nt < 16; nt++) {
            o[nt][0] *= sc0; o[nt][1] *= sc0;
            o[nt][2] *= sc1; o[nt][3] *= sc1;
        }

        // ---- pack P -> bf16 hi/lo A-frags ----
        uint32_t aph[4][4], apl[4][4];
        #pragma unroll
        for (int ks = 0; ks < 4; ks++) {
            #pragma unroll
            for (int half = 0; half < 2; half++) {
                float x0 = s[2*ks + half][0], x1 = s[2*ks + half][1];
                float x2 = s[2*ks + half][2], x3 = s[2*ks + half][3];
                uint32_t h01 = pack_bf2(x0, x1);
                uint32_t h23 = pack_bf2(x2, x3);
                __nv_bfloat162 hb01, hb23;
                memcpy(&hb01, &h01, 4);
                memcpy(&hb23, &h23, 4);
                aph[ks][half * 2 + 0] = h01;
                aph[ks][half * 2 + 1] = h23;
                apl[ks][half * 2 + 0] =
                    pack_bf2(x0 - __bfloat162float(hb01.x),
                             x1 - __bfloat162float(hb01.y));
                apl[ks][half * 2 + 1] =
                    pack_bf2(x2 - __bfloat162float(hb23.x),
                             x3 - __bfloat162float(hb23.y));
            }
        }

        // ---- O += P V (3-term) ----
        const uint32_t vb = stgb + 2 * AT_SUBT + vt_off;
        #pragma unroll
        for (int ks = 0; ks < 4; ks++) {
            #pragma unroll
            for (int dt2 = 0; dt2 < 8; dt2++) {
                uint32_t a = vb + (uint32_t)ks * (16 * AT_STRIDE) + dt2 * 32;
                uint32_t vf[4];
                LDSM4T(vf, a);              // V hi
                MMA16816(o[2*dt2],   aph[ks], vf[0], vf[1]);
                MMA16816(o[2*dt2+1], aph[ks], vf[2], vf[3]);
                MMA16816(o[2*dt2],   apl[ks], vf[0], vf[1]);
                MMA16816(o[2*dt2+1], apl[ks], vf[2], vf[3]);
                LDSM4T(vf, a + AT_SUBT);    // V lo
                MMA16816(o[2*dt2],   aph[ks], vf[0], vf[1]);
                MMA16816(o[2*dt2+1], aph[ks], vf[2], vf[3]);
            }
        }
        __syncthreads();   // all warps done with stage 'cur' before its reuse
    }

    // ---- epilogue ----
    float i0v = 1.0f / l0, i1v = 1.0f / l1;
    size_t tok0 = (size_t)(b * S_ + rbase0);
    float* d0 = g_ao + tok0 * (H_ * D_) + h * D_;
    float* d1 = d0 + 8 * (size_t)(H_ * D_);
    #pragma unroll
    for (int nt = 0; nt < 16; nt++) {
        int colb = nt * 8 + 2 * (lane & 3);
        *reinterpret_cast<float2*>(d0 + colb) =
            make_float2(o[nt][0] * i0v, o[nt][1] * i0v);
        *reinterpret_cast<float2*>(d1 + colb) =
            make_float2(o[nt][2] * i1v, o[nt][3] * i1v);
    }
}

// ---------------------------------------------------------------------------
extern "C" void kernel_launch(void* const* d_in, const int* in_sizes, int n_in,
                              void* d_out, int out_size)
{
    const float* hidden = (const float*)d_in[0];
    const int*   pos    = (const int*)  d_in[1];
    const float* wq     = (const float*)d_in[2];
    const float* wk     = (const float*)d_in[3];
    const float* wv     = (const float*)d_in[4];
    const float* wo     = (const float*)d_in[5];
    float* out = (float*)d_out;

    float *gqkv, *gao;
    __nv_bfloat16 *ahi, *alo, *wqkvh, *wqkvl, *woh, *wol;
    cudaGetSymbolAddress((void**)&gqkv,  g_qkv);
    cudaGetSymbolAddress((void**)&gao,   g_ao);
    cudaGetSymbolAddress((void**)&ahi,   g_Ahi);
    cudaGetSymbolAddress((void**)&alo,   g_Alo);
    cudaGetSymbolAddress((void**)&wqkvh, g_Wqkvhi);
    cudaGetSymbolAddress((void**)&wqkvl, g_Wqkvlo);
    cudaGetSymbolAddress((void**)&woh,   g_Wohi);
    cudaGetSymbolAddress((void**)&wol,   g_Wolo);

    cudaFuncSetAttribute(gemm_split_kernel,
                         cudaFuncAttributeMaxDynamicSharedMemorySize, GEMM_SMEM);
    cudaFuncSetAttribute(attn_mma_kernel,
                         cudaFuncAttributeMaxDynamicSharedMemorySize, AT_SMEM);

    // ---- split inputs ----
    split_kernel<<<(M_TOK * HID_ / 4 + 255) / 256, 256>>>(hidden, ahi, alo,
                                                          M_TOK * HID_ / 4);
    split_T_kernel<<<dim3((H_*D_)/32,  HID_/32), dim3(32, 8)>>>(
        wq, wqkvh, wqkvl, HID_, H_*D_);
    split_T_kernel<<<dim3((KH_*D_)/32, HID_/32), dim3(32, 8)>>>(
        wk, wqkvh + (size_t)(H_*D_) * HID_, wqkvl + (size_t)(H_*D_) * HID_,
        HID_, KH_*D_);
    split_T_kernel<<<dim3((KH_*D_)/32, HID_/32), dim3(32, 8)>>>(
        wv, wqkvh + (size_t)(H_*D_ + KH_*D_) * HID_,
        wqkvl + (size_t)(H_*D_ + KH_*D_) * HID_, HID_, KH_*D_);
    split_T_kernel<<<dim3(HID_/32, (H_*D_)/32), dim3(32, 8)>>>(
        wo, woh, wol, H_*D_, HID_);

    // ---- fused QKV projection ----
    gemm_split_kernel<<<dim3(NQKV/128, M_TOK/128), 256, GEMM_SMEM>>>(
        ahi, alo, wqkvh, wqkvl, gqkv, M_TOK, NQKV, HID_);

    // ---- RoPE + attention-operand splits ----
    {
        int total = M_TOK * (H_*64 + KH_*64 + KH_*64);
        rope_split_kernel<<<(total + 255) / 256, 256>>>(pos);
    }

    // ---- attention (HMMA) ----
    attn_mma_kernel<<<dim3(S_ / 128, H_, B_), 256, AT_SMEM>>>();

    // ---- output projection ----
    split_kernel<<<(M_TOK * HID_ / 4 + 255) / 256, 256>>>(gao, ahi, alo,
                                                          M_TOK * HID_ / 4);
    gemm_split_kernel<<<dim3(HID_/128, M_TOK/128), 256, GEMM_SMEM>>>(
        ahi, alo, woh, wol, out, M_TOK, HID_, H_*D_);
}